// round 5
// baseline (speedup 1.0000x reference)
#include <cuda_runtime.h>
#include <cuda_bf16.h>
#include <mma.h>
#include <cstdint>

using namespace nvcuda;

// Problem constants
#define MM     8192      // BATCH*SEQ
#define DMODEL 1024
#define DINNER 2048
#define DSTATE 16
#define NBATCH 4
#define SEQLEN 2048

// ---------------- scratch (device globals: allocation-free) ----------------
__device__ float g_u  [MM * DINNER];      // silu(x_proj), tf32-rounded
__device__ float g_sz [MM * DINNER];      // silu(z), full precision
__device__ float g_dt [MM * DINNER];      // softplus(dt)
__device__ float g_xd [MM * 32];          // [B|C] projection
__device__ float g_ym [MM * DINNER];      // y * silu(z), tf32-rounded
__device__ float g_x32[MM * DMODEL];      // tf32-rounded x
__device__ float g_w1 [DMODEL * 4096];    // tf32-rounded W_in   [1024][4096]
__device__ float g_w2 [DINNER * DINNER];  // tf32-rounded W_dt   [2048][2048]
__device__ float g_w3 [DINNER * DMODEL];  // tf32-rounded W_out  [2048][1024]

__device__ __forceinline__ float siluf(float v) { return v / (1.f + __expf(-v)); }
__device__ __forceinline__ float softplusf(float v) {
    return fmaxf(v, 0.f) + log1pf(__expf(-fabsf(v)));
}
__device__ __forceinline__ float ex2(float x) {
    float r; asm("ex2.approx.f32 %0, %1;" : "=f"(r) : "f"(x)); return r;
}
__device__ __forceinline__ float tf32r(float v) {
    unsigned u; asm("cvt.rna.tf32.f32 %0, %1;" : "=r"(u) : "f"(v));
    return __uint_as_float(u);
}

// ---------------- cp.async helpers ----------------------------------------
__device__ __forceinline__ void cp16(void* s, const void* g) {
    unsigned sa = (unsigned)__cvta_generic_to_shared(s);
    asm volatile("cp.async.cg.shared.global [%0], [%1], 16;\n" :: "r"(sa), "l"(g));
}
__device__ __forceinline__ void cp_commit() {
    asm volatile("cp.async.commit_group;\n" ::: "memory");
}
template<int N> __device__ __forceinline__ void cp_wait() {
    asm volatile("cp.async.wait_group %0;\n" :: "n"(N) : "memory");
}

// ---------------- tf32 WMMA GEMM v2 ----------------------------------------
// C = A[MxK] @ B[KxN] + bias. Operands pre-rounded to tf32 (no in-loop cvt).
// 4 warps, warp tile 64x64 (4x4 frags of 16x16x8). Block tile 128x128x32,
// 2-stage cp.async. Epilogues:
//   EPI 0: silu; cols<2048 -> out0 (tf32-rounded), else -> out1 (full)
//   EPI 1: softplus -> out0
//   EPI 2: plain    -> out0
constexpr int AS_STRIDE = 40;                // 32 + 8 pad
constexpr int BS_STRIDE = 136;               // 128 + 8 pad
constexpr int AS_TILE   = 128 * AS_STRIDE;   // 5120 floats
constexpr int BS_TILE   = 32 * BS_STRIDE;    // 4352 floats
constexpr int EPI_FLOATS = 4 * 256;          // 1024 floats
constexpr int GEMM_SMEM_BYTES =
    (2 * AS_TILE + 2 * BS_TILE + EPI_FLOATS) * 4;   // 79872 B -> 2 CTAs/SM

template<int EPI>
__global__ __launch_bounds__(128) void gemm_tf32(
    const float* __restrict__ A, const float* __restrict__ B,
    const float* __restrict__ bias,
    float* __restrict__ out0, float* __restrict__ out1,
    int M, int N, int K)
{
    extern __shared__ float smem[];
    float* As  = smem;                              // [2][128][40]
    float* Bs  = smem + 2 * AS_TILE;                // [2][32][136]
    float* Epi = smem + 2 * AS_TILE + 2 * BS_TILE;  // [4][16][16]

    const int tid  = threadIdx.x;
    const int wid  = tid >> 5;       // 0..3
    const int lane = tid & 31;
    const int wm   = wid >> 1;       // 0..1 -> 64-row half
    const int wn   = wid & 1;        // 0..1 -> 64-col half
    const int m0   = blockIdx.y * 128;
    const int n0   = blockIdx.x * 128;

    // per-thread load coordinates
    const int arow = tid >> 3;            // + r*16 rows (8 iters)
    const int acol = (tid & 7) << 2;
    const int brow = tid >> 5;            // + r*4 rows (8 iters)
    const int bcol = (tid & 31) << 2;

    wmma::fragment<wmma::accumulator, 16, 16, 8, float> acc[4][4];
    #pragma unroll
    for (int i = 0; i < 4; i++)
        #pragma unroll
        for (int j = 0; j < 4; j++)
            wmma::fill_fragment(acc[i][j], 0.f);

    const int NIT = K >> 5;

    auto load_ab = [&](int buf, int k0) {
        float* da = As + buf * AS_TILE;
        float* db = Bs + buf * BS_TILE;
        #pragma unroll
        for (int r = 0; r < 8; r++) {
            int row = arow + r * 16;
            cp16(&da[row * AS_STRIDE + acol],
                 &A[(size_t)(m0 + row) * K + k0 + acol]);
        }
        #pragma unroll
        for (int r = 0; r < 8; r++) {
            int row = brow + r * 4;
            cp16(&db[row * BS_STRIDE + bcol],
                 &B[(size_t)(k0 + row) * N + n0 + bcol]);
        }
        cp_commit();
    };

    load_ab(0, 0);   // prologue

    for (int it = 0; it < NIT; it++) {
        const int buf = it & 1;
        if (it + 1 < NIT) {
            load_ab(buf ^ 1, (it + 1) << 5);
            cp_wait<1>();
        } else {
            cp_wait<0>();
        }
        __syncthreads();

        const float* ca = As + buf * AS_TILE;
        const float* cb = Bs + buf * BS_TILE;
        #pragma unroll
        for (int kk = 0; kk < 32; kk += 8) {
            wmma::fragment<wmma::matrix_a, 16, 16, 8, wmma::precision::tf32, wmma::row_major> af[4];
            wmma::fragment<wmma::matrix_b, 16, 16, 8, wmma::precision::tf32, wmma::row_major> bf[4];
            #pragma unroll
            for (int i = 0; i < 4; i++)
                wmma::load_matrix_sync(af[i],
                    &ca[(wm * 64 + i * 16) * AS_STRIDE + kk], AS_STRIDE);
            #pragma unroll
            for (int j = 0; j < 4; j++)
                wmma::load_matrix_sync(bf[j],
                    &cb[kk * BS_STRIDE + wn * 64 + j * 16], BS_STRIDE);
            // operands pre-rounded to tf32: no cvt loops needed
            #pragma unroll
            for (int i = 0; i < 4; i++)
                #pragma unroll
                for (int j = 0; j < 4; j++)
                    wmma::mma_sync(acc[i][j], af[i], bf[j], acc[i][j]);
        }
        __syncthreads();
    }

    // Epilogue: frag-by-frag through per-warp smem
    float* EpiW = Epi + wid * 256;
    #pragma unroll
    for (int i = 0; i < 4; i++) {
        #pragma unroll
        for (int j = 0; j < 4; j++) {
            wmma::store_matrix_sync(EpiW, acc[i][j], 16, wmma::mem_row_major);
            __syncwarp();
            int gr0 = m0 + wm * 64 + i * 16;
            int gc0 = n0 + wn * 64 + j * 16;
            #pragma unroll
            for (int e = 0; e < 8; e++) {
                int idx = lane + e * 32;
                int r = idx >> 4, c = idx & 15;
                int gr = gr0 + r, gc = gc0 + c;
                float v = EpiW[r * 16 + c] + bias[gc];
                if (EPI == 0) {
                    float sv = siluf(v);
                    if (gc < DINNER) out0[(size_t)gr * DINNER + gc] = tf32r(sv);
                    else             out1[(size_t)gr * DINNER + gc - DINNER] = sv;
                } else if (EPI == 1) {
                    out0[(size_t)gr * DINNER + gc] = softplusf(v);
                } else {
                    out0[(size_t)gr * (size_t)N + gc] = v;
                }
            }
            __syncwarp();
        }
    }
}

// ---------------- prep: tf32-round copies ----------------------------------
__global__ __launch_bounds__(256) void round_copy(
    const float* __restrict__ src, float* __restrict__ dst)
{
    int i = (blockIdx.x * 256 + threadIdx.x) * 4;
    float4 v = *(const float4*)&src[i];
    v.x = tf32r(v.x); v.y = tf32r(v.y); v.z = tf32r(v.z); v.w = tf32r(v.w);
    *(float4*)&dst[i] = v;
}

// ---------------- skinny projection: xdbl = u @ W_xproj + b ----------------
__global__ __launch_bounds__(256) void xproj_kernel(
    const float* __restrict__ u, const float* __restrict__ W,
    const float* __restrict__ bias, float* __restrict__ xdbl)
{
    __shared__ float Ws[32][33];
    const int wid  = threadIdx.x >> 5;
    const int lane = threadIdx.x & 31;
    const int row  = blockIdx.x * 8 + wid;

    float acc = 0.f;
    for (int k0 = 0; k0 < DINNER; k0 += 32) {
        #pragma unroll
        for (int r = 0; r < 4; r++) {
            int idx = threadIdx.x + r * 256;
            Ws[idx >> 5][idx & 31] = W[(size_t)(k0 + (idx >> 5)) * 32 + (idx & 31)];
        }
        __syncthreads();
        float a = u[(size_t)row * DINNER + k0 + lane];
        #pragma unroll
        for (int i = 0; i < 32; i++)
            acc = fmaf(__shfl_sync(0xffffffffu, a, i), Ws[i][lane], acc);
        __syncthreads();
    }
    xdbl[(size_t)row * 32 + lane] = acc + bias[lane];
}

// ---------------- selective scan (fused * silu(z)) -------------------------
__global__ __launch_bounds__(256) void scan_kernel(
    const float* __restrict__ u, const float* __restrict__ dt,
    const float* __restrict__ xdbl, const float* __restrict__ sz,
    const float* __restrict__ A_log, const float* __restrict__ Dp,
    float* __restrict__ ym)
{
    __shared__ float XD[32][32];
    __shared__ float Us[32][64];
    __shared__ float Ts[32][64];
    __shared__ float Zs[32][64];

    const int b    = blockIdx.y;
    const int d0   = blockIdx.x * 64;
    const int tid  = threadIdx.x;
    const int wid  = tid >> 5;
    const int lane = tid & 31;
    const int dq   = lane >> 2;
    const int sq   = lane & 3;
    const int dl   = wid * 8 + dq;
    const int d    = d0 + dl;

    float Ap[4], h[4] = {0.f, 0.f, 0.f, 0.f};
    #pragma unroll
    for (int i = 0; i < 4; i++)
        Ap[i] = -__expf(A_log[d * DSTATE + sq * 4 + i]) * 1.4426950408889634f;
    const float Dv = Dp[d];
    const size_t base = (size_t)b * SEQLEN * DINNER;

    for (int t0 = 0; t0 < SEQLEN; t0 += 32) {
        #pragma unroll
        for (int r = 0; r < 4; r++) {
            int idx = tid + r * 256;
            XD[idx >> 5][idx & 31] =
                xdbl[((size_t)b * SEQLEN + t0 + (idx >> 5)) * 32 + (idx & 31)];
        }
        #pragma unroll
        for (int r = 0; r < 8; r++) {
            int idx = tid + r * 256;
            int tt = idx >> 6, j = idx & 63;
            size_t g = base + (size_t)(t0 + tt) * DINNER + d0 + j;
            Us[tt][j] = u[g];
            Ts[tt][j] = dt[g];
            Zs[tt][j] = sz[g];
        }
        __syncthreads();

        #pragma unroll 4
        for (int t = 0; t < 32; t++) {
            float dtv = Ts[t][dl];
            float uv  = Us[t][dl];
            float du  = dtv * uv;
            float p   = 0.f;
            #pragma unroll
            for (int i = 0; i < 4; i++) {
                float e = ex2(dtv * Ap[i]);
                h[i] = fmaf(h[i], e, du * XD[t][sq * 4 + i]);
                p    = fmaf(h[i], XD[t][16 + sq * 4 + i], p);
            }
            p += __shfl_xor_sync(0xffffffffu, p, 1);
            p += __shfl_xor_sync(0xffffffffu, p, 2);
            if (sq == 0) {
                float y = p + Dv * uv;
                ym[base + (size_t)(t0 + t) * DINNER + d] = tf32r(y * Zs[t][dl]);
            }
        }
        __syncthreads();
    }
}

// ---------------- launch ---------------------------------------------------
extern "C" void kernel_launch(void* const* d_in, const int* in_sizes, int n_in,
                              void* d_out, int out_size)
{
    const float* x     = (const float*)d_in[0];
    const float* W_in  = (const float*)d_in[1];
    const float* b_in  = (const float*)d_in[2];
    const float* W_xp  = (const float*)d_in[3];
    const float* b_xp  = (const float*)d_in[4];
    const float* W_dt  = (const float*)d_in[5];
    const float* b_dt  = (const float*)d_in[6];
    const float* W_out = (const float*)d_in[7];
    const float* b_out = (const float*)d_in[8];
    const float* A_log = (const float*)d_in[9];
    const float* D_par = (const float*)d_in[10];
    float* out = (float*)d_out;

    float *u, *sz, *dtb, *xd, *ym, *x32, *w1, *w2, *w3;
    cudaGetSymbolAddress((void**)&u,   g_u);
    cudaGetSymbolAddress((void**)&sz,  g_sz);
    cudaGetSymbolAddress((void**)&dtb, g_dt);
    cudaGetSymbolAddress((void**)&xd,  g_xd);
    cudaGetSymbolAddress((void**)&ym,  g_ym);
    cudaGetSymbolAddress((void**)&x32, g_x32);
    cudaGetSymbolAddress((void**)&w1,  g_w1);
    cudaGetSymbolAddress((void**)&w2,  g_w2);
    cudaGetSymbolAddress((void**)&w3,  g_w3);

    cudaFuncSetAttribute(gemm_tf32<0>, cudaFuncAttributeMaxDynamicSharedMemorySize, GEMM_SMEM_BYTES);
    cudaFuncSetAttribute(gemm_tf32<1>, cudaFuncAttributeMaxDynamicSharedMemorySize, GEMM_SMEM_BYTES);
    cudaFuncSetAttribute(gemm_tf32<2>, cudaFuncAttributeMaxDynamicSharedMemorySize, GEMM_SMEM_BYTES);

    // prep: tf32-round x and weights (once per launch, ~6 MB + 40 MB traffic)
    round_copy<<<MM * DMODEL / 1024, 256>>>(x, x32);
    round_copy<<<DMODEL * 4096 / 1024, 256>>>(W_in, w1);
    round_copy<<<DINNER * DINNER / 1024, 256>>>(W_dt, w2);
    round_copy<<<DINNER * DMODEL / 1024, 256>>>(W_out, w3);

    dim3 blk(128);

    // 1) xz = x @ W_in + b_in; split; silu -> u (tf32-rounded), sz (full)
    gemm_tf32<0><<<dim3(4096 / 128, MM / 128), blk, GEMM_SMEM_BYTES>>>(
        x32, w1, b_in, u, sz, MM, 4096, DMODEL);

    // 2) xdbl = u @ W_xproj + b_xproj
    xproj_kernel<<<MM / 8, 256>>>(u, W_xp, b_xp, xd);

    // 3) dt = softplus(u @ W_dt + b_dt)
    gemm_tf32<1><<<dim3(DINNER / 128, MM / 128), blk, GEMM_SMEM_BYTES>>>(
        u, w2, b_dt, dtb, nullptr, MM, DINNER, DINNER);

    // 4) selective scan + fuse * silu(z)  (ym tf32-rounded)
    scan_kernel<<<dim3(DINNER / 64, NBATCH), 256>>>(
        u, dtb, xd, sz, A_log, D_par, ym);

    // 5) out = ym @ W_out + b_out
    gemm_tf32<2><<<dim3(DMODEL / 128, MM / 128), blk, GEMM_SMEM_BYTES>>>(
        ym, w3, b_out, out, nullptr, MM, DMODEL, DINNER);
}

// round 6
// speedup vs baseline: 2.6761x; 2.6761x over previous
#include <cuda_runtime.h>
#include <cuda_fp16.h>
#include <mma.h>
#include <cstdint>

using namespace nvcuda;

// Problem constants
#define MM     8192      // BATCH*SEQ
#define DMODEL 1024
#define DINNER 2048
#define DSTATE 16
#define NBATCH 4
#define SEQLEN 2048

// ---------------- scratch (device globals: allocation-free) ----------------
__device__ float  g_u  [MM * DINNER];      // silu(x_proj) fp32 (scan/xproj)
__device__ __half g_uh [MM * DINNER];      // silu(x_proj) half (dt GEMM)
__device__ float  g_sz [MM * DINNER];      // silu(z)
__device__ float  g_dt [MM * DINNER];      // softplus(dt)
__device__ float  g_xd [MM * 32];          // [B|C] projection
__device__ __half g_ymh[MM * DINNER];      // y * silu(z) half (out GEMM)
__device__ __half g_xh [MM * DMODEL];      // half x
__device__ __half g_w1 [DMODEL * 4096];    // half W_in
__device__ __half g_w2 [DINNER * DINNER];  // half W_dt
__device__ __half g_w3 [DINNER * DMODEL];  // half W_out

__device__ __forceinline__ float siluf(float v) { return v / (1.f + __expf(-v)); }
__device__ __forceinline__ float softplusf(float v) {
    return fmaxf(v, 0.f) + log1pf(__expf(-fabsf(v)));
}
__device__ __forceinline__ float ex2(float x) {
    float r; asm("ex2.approx.f32 %0, %1;" : "=f"(r) : "f"(x)); return r;
}

// ---------------- cp.async helpers ----------------------------------------
__device__ __forceinline__ void cp16(void* s, const void* g) {
    unsigned sa = (unsigned)__cvta_generic_to_shared(s);
    asm volatile("cp.async.cg.shared.global [%0], [%1], 16;\n" :: "r"(sa), "l"(g));
}
__device__ __forceinline__ void cp_commit() {
    asm volatile("cp.async.commit_group;\n" ::: "memory");
}
template<int N> __device__ __forceinline__ void cp_wait() {
    asm volatile("cp.async.wait_group %0;\n" :: "n"(N) : "memory");
}

// ---------------- fp16 WMMA GEMM -------------------------------------------
// C = A[MxK] @ B[KxN] + bias (A,B half; accum fp32).
// 8 warps, warp tile 64x32 (4x2 frags of 16x16x16). Block tile 128x128x32,
// 2-stage cp.async double buffer.
// EPI 0: silu; cols<2048 -> u (f32 + half), else -> sz (f32)
// EPI 1: softplus -> out0 f32
// EPI 2: plain    -> out0 f32
constexpr int AS_STRIDE = 40;                 // halves: 32 + 8 pad (16B)
constexpr int BS_STRIDE = 136;                // halves: 128 + 8 pad
constexpr int AS_TILE   = 128 * AS_STRIDE;    // 5120 halves
constexpr int BS_TILE   = 32 * BS_STRIDE;     // 4352 halves
constexpr int EPI_BYTES = 8 * 256 * 4;        // 8192 B
constexpr int GEMM_SMEM_BYTES =
    (2 * AS_TILE + 2 * BS_TILE) * 2 + EPI_BYTES;   // 46080 B -> 4 CTAs/SM

template<int EPI>
__global__ __launch_bounds__(256) void gemm_fp16(
    const __half* __restrict__ A, const __half* __restrict__ B,
    const float* __restrict__ bias,
    float* __restrict__ out0, float* __restrict__ out1,
    __half* __restrict__ out0h,
    int M, int N, int K)
{
    extern __shared__ char smem[];
    __half* As = (__half*)smem;                         // [2][128][40]
    __half* Bs = (__half*)smem + 2 * AS_TILE;           // [2][32][136]
    float*  Epi = (float*)(smem + (2 * AS_TILE + 2 * BS_TILE) * 2);

    const int tid  = threadIdx.x;
    const int wid  = tid >> 5;   // 0..7
    const int lane = tid & 31;
    const int wm   = wid >> 2;   // 0..1 -> 64-row half
    const int wn   = wid & 3;    // 0..3 -> 32-col quarter
    const int m0   = blockIdx.y * 128;
    const int n0   = blockIdx.x * 128;

    // load coords: A 128x32 halves (512 cp16, 2/thread), B 32x128 (512, 2/thr)
    const int arow = tid >> 2;            // + r*64
    const int ac16 = tid & 3;             // 8-half chunk
    const int brow = tid >> 4;            // + r*16
    const int bc16 = tid & 15;

    wmma::fragment<wmma::accumulator, 16, 16, 16, float> acc[4][2];
    #pragma unroll
    for (int i = 0; i < 4; i++)
        #pragma unroll
        for (int j = 0; j < 2; j++)
            wmma::fill_fragment(acc[i][j], 0.f);

    const int NIT = K >> 5;

    auto load_ab = [&](int buf, int k0) {
        __half* da = As + buf * AS_TILE;
        __half* db = Bs + buf * BS_TILE;
        #pragma unroll
        for (int r = 0; r < 2; r++) {
            int row = arow + r * 64;
            cp16(&da[row * AS_STRIDE + ac16 * 8],
                 &A[(size_t)(m0 + row) * K + k0 + ac16 * 8]);
        }
        #pragma unroll
        for (int r = 0; r < 2; r++) {
            int row = brow + r * 16;
            cp16(&db[row * BS_STRIDE + bc16 * 8],
                 &B[(size_t)(k0 + row) * N + n0 + bc16 * 8]);
        }
        cp_commit();
    };

    load_ab(0, 0);

    for (int it = 0; it < NIT; it++) {
        const int buf = it & 1;
        if (it + 1 < NIT) {
            load_ab(buf ^ 1, (it + 1) << 5);
            cp_wait<1>();
        } else {
            cp_wait<0>();
        }
        __syncthreads();

        const __half* ca = As + buf * AS_TILE;
        const __half* cb = Bs + buf * BS_TILE;
        #pragma unroll
        for (int kk = 0; kk < 32; kk += 16) {
            wmma::fragment<wmma::matrix_a, 16, 16, 16, __half, wmma::row_major> af[4];
            wmma::fragment<wmma::matrix_b, 16, 16, 16, __half, wmma::row_major> bf[2];
            #pragma unroll
            for (int i = 0; i < 4; i++)
                wmma::load_matrix_sync(af[i],
                    &ca[(wm * 64 + i * 16) * AS_STRIDE + kk], AS_STRIDE);
            #pragma unroll
            for (int j = 0; j < 2; j++)
                wmma::load_matrix_sync(bf[j],
                    &cb[kk * BS_STRIDE + wn * 32 + j * 16], BS_STRIDE);
            #pragma unroll
            for (int i = 0; i < 4; i++)
                #pragma unroll
                for (int j = 0; j < 2; j++)
                    wmma::mma_sync(acc[i][j], af[i], bf[j], acc[i][j]);
        }
        __syncthreads();
    }

    // Epilogue: frag-by-frag through per-warp smem
    float* EpiW = Epi + wid * 256;
    #pragma unroll
    for (int i = 0; i < 4; i++) {
        #pragma unroll
        for (int j = 0; j < 2; j++) {
            wmma::store_matrix_sync(EpiW, acc[i][j], 16, wmma::mem_row_major);
            __syncwarp();
            int gr0 = m0 + wm * 64 + i * 16;
            int gc0 = n0 + wn * 32 + j * 16;
            #pragma unroll
            for (int e = 0; e < 8; e++) {
                int idx = lane + e * 32;
                int r = idx >> 4, c = idx & 15;
                int gr = gr0 + r, gc = gc0 + c;
                float v = EpiW[r * 16 + c] + bias[gc];
                if (EPI == 0) {
                    float sv = siluf(v);
                    if (gc < DINNER) {
                        size_t o = (size_t)gr * DINNER + gc;
                        out0 [o] = sv;
                        out0h[o] = __float2half(sv);
                    } else {
                        out1[(size_t)gr * DINNER + gc - DINNER] = sv;
                    }
                } else if (EPI == 1) {
                    out0[(size_t)gr * DINNER + gc] = softplusf(v);
                } else {
                    out0[(size_t)gr * (size_t)N + gc] = v;
                }
            }
            __syncwarp();
        }
    }
}

// ---------------- prep: fp32 -> fp16 copies --------------------------------
__global__ __launch_bounds__(256) void half_copy(
    const float* __restrict__ src, __half* __restrict__ dst)
{
    int i = (blockIdx.x * 256 + threadIdx.x) * 8;
    float4 a = *(const float4*)&src[i];
    float4 b = *(const float4*)&src[i + 4];
    __half2 h[4];
    h[0] = __floats2half2_rn(a.x, a.y);
    h[1] = __floats2half2_rn(a.z, a.w);
    h[2] = __floats2half2_rn(b.x, b.y);
    h[3] = __floats2half2_rn(b.z, b.w);
    *(uint4*)&dst[i] = *(uint4*)h;
}

// ---------------- skinny projection: xdbl = u @ W_xproj + b ----------------
__global__ __launch_bounds__(256) void xproj_kernel(
    const float* __restrict__ u, const float* __restrict__ W,
    const float* __restrict__ bias, float* __restrict__ xdbl)
{
    __shared__ float Ws[32][33];
    const int wid  = threadIdx.x >> 5;
    const int lane = threadIdx.x & 31;
    const int row  = blockIdx.x * 8 + wid;

    float acc = 0.f;
    for (int k0 = 0; k0 < DINNER; k0 += 32) {
        #pragma unroll
        for (int r = 0; r < 4; r++) {
            int idx = threadIdx.x + r * 256;
            Ws[idx >> 5][idx & 31] = W[(size_t)(k0 + (idx >> 5)) * 32 + (idx & 31)];
        }
        __syncthreads();
        float a = u[(size_t)row * DINNER + k0 + lane];
        #pragma unroll
        for (int i = 0; i < 32; i++)
            acc = fmaf(__shfl_sync(0xffffffffu, a, i), Ws[i][lane], acc);
        __syncthreads();
    }
    xdbl[(size_t)row * 32 + lane] = acc + bias[lane];
}

// ---------------- selective scan (fused * silu(z)) -------------------------
__global__ __launch_bounds__(256) void scan_kernel(
    const float* __restrict__ u, const float* __restrict__ dt,
    const float* __restrict__ xdbl, const float* __restrict__ sz,
    const float* __restrict__ A_log, const float* __restrict__ Dp,
    __half* __restrict__ ymh)
{
    __shared__ float XD[32][32];
    __shared__ float Us[32][64];
    __shared__ float Ts[32][64];
    __shared__ float Zs[32][64];

    const int b    = blockIdx.y;
    const int d0   = blockIdx.x * 64;
    const int tid  = threadIdx.x;
    const int wid  = tid >> 5;
    const int lane = tid & 31;
    const int dq   = lane >> 2;
    const int sq   = lane & 3;
    const int dl   = wid * 8 + dq;
    const int d    = d0 + dl;

    float Ap[4], h[4] = {0.f, 0.f, 0.f, 0.f};
    #pragma unroll
    for (int i = 0; i < 4; i++)
        Ap[i] = -__expf(A_log[d * DSTATE + sq * 4 + i]) * 1.4426950408889634f;
    const float Dv = Dp[d];
    const size_t base = (size_t)b * SEQLEN * DINNER;

    for (int t0 = 0; t0 < SEQLEN; t0 += 32) {
        #pragma unroll
        for (int r = 0; r < 4; r++) {
            int idx = tid + r * 256;
            XD[idx >> 5][idx & 31] =
                xdbl[((size_t)b * SEQLEN + t0 + (idx >> 5)) * 32 + (idx & 31)];
        }
        #pragma unroll
        for (int r = 0; r < 8; r++) {
            int idx = tid + r * 256;
            int tt = idx >> 6, j = idx & 63;
            size_t g = base + (size_t)(t0 + tt) * DINNER + d0 + j;
            Us[tt][j] = u[g];
            Ts[tt][j] = dt[g];
            Zs[tt][j] = sz[g];
        }
        __syncthreads();

        #pragma unroll 4
        for (int t = 0; t < 32; t++) {
            float dtv = Ts[t][dl];
            float uv  = Us[t][dl];
            float du  = dtv * uv;
            float p   = 0.f;
            #pragma unroll
            for (int i = 0; i < 4; i++) {
                float e = ex2(dtv * Ap[i]);
                h[i] = fmaf(h[i], e, du * XD[t][sq * 4 + i]);
                p    = fmaf(h[i], XD[t][16 + sq * 4 + i], p);
            }
            p += __shfl_xor_sync(0xffffffffu, p, 1);
            p += __shfl_xor_sync(0xffffffffu, p, 2);
            if (sq == 0) {
                float y = p + Dv * uv;
                ymh[base + (size_t)(t0 + t) * DINNER + d] = __float2half(y * Zs[t][dl]);
            }
        }
        __syncthreads();
    }
}

// ---------------- launch ---------------------------------------------------
extern "C" void kernel_launch(void* const* d_in, const int* in_sizes, int n_in,
                              void* d_out, int out_size)
{
    const float* x     = (const float*)d_in[0];
    const float* W_in  = (const float*)d_in[1];
    const float* b_in  = (const float*)d_in[2];
    const float* W_xp  = (const float*)d_in[3];
    const float* b_xp  = (const float*)d_in[4];
    const float* W_dt  = (const float*)d_in[5];
    const float* b_dt  = (const float*)d_in[6];
    const float* W_out = (const float*)d_in[7];
    const float* b_out = (const float*)d_in[8];
    const float* A_log = (const float*)d_in[9];
    const float* D_par = (const float*)d_in[10];
    float* out = (float*)d_out;

    float *u, *sz, *dtb, *xd;
    __half *uh, *ymh, *xh, *w1, *w2, *w3;
    cudaGetSymbolAddress((void**)&u,   g_u);
    cudaGetSymbolAddress((void**)&uh,  g_uh);
    cudaGetSymbolAddress((void**)&sz,  g_sz);
    cudaGetSymbolAddress((void**)&dtb, g_dt);
    cudaGetSymbolAddress((void**)&xd,  g_xd);
    cudaGetSymbolAddress((void**)&ymh, g_ymh);
    cudaGetSymbolAddress((void**)&xh,  g_xh);
    cudaGetSymbolAddress((void**)&w1,  g_w1);
    cudaGetSymbolAddress((void**)&w2,  g_w2);
    cudaGetSymbolAddress((void**)&w3,  g_w3);

    cudaFuncSetAttribute(gemm_fp16<0>, cudaFuncAttributeMaxDynamicSharedMemorySize, GEMM_SMEM_BYTES);
    cudaFuncSetAttribute(gemm_fp16<1>, cudaFuncAttributeMaxDynamicSharedMemorySize, GEMM_SMEM_BYTES);
    cudaFuncSetAttribute(gemm_fp16<2>, cudaFuncAttributeMaxDynamicSharedMemorySize, GEMM_SMEM_BYTES);

    // prep: half copies of x and weights
    half_copy<<<MM * DMODEL / 2048, 256>>>(x, xh);
    half_copy<<<DMODEL * 4096 / 2048, 256>>>(W_in, w1);
    half_copy<<<DINNER * DINNER / 2048, 256>>>(W_dt, w2);
    half_copy<<<DINNER * DMODEL / 2048, 256>>>(W_out, w3);

    dim3 blk(256);

    // 1) xz = x @ W_in + b_in; split+silu -> u (f32 + half), sz (f32)
    gemm_fp16<0><<<dim3(4096 / 128, MM / 128), blk, GEMM_SMEM_BYTES>>>(
        xh, w1, b_in, u, sz, uh, MM, 4096, DMODEL);

    // 2) xdbl = u @ W_xproj + b_xproj  (fp32 path)
    xproj_kernel<<<MM / 8, 256>>>(u, W_xp, b_xp, xd);

    // 3) dt = softplus(u @ W_dt + b_dt)
    gemm_fp16<1><<<dim3(DINNER / 128, MM / 128), blk, GEMM_SMEM_BYTES>>>(
        uh, w2, b_dt, dtb, nullptr, nullptr, MM, DINNER, DINNER);

    // 4) selective scan + fuse * silu(z) -> ym half
    scan_kernel<<<dim3(DINNER / 64, NBATCH), 256>>>(
        u, dtb, xd, sz, A_log, D_par, ymh);

    // 5) out = ym @ W_out + b_out
    gemm_fp16<2><<<dim3(DMODEL / 128, MM / 128), blk, GEMM_SMEM_BYTES>>>(
        ymh, w3, b_out, out, nullptr, nullptr, MM, DMODEL, DINNER);
}

// round 7
// speedup vs baseline: 2.9577x; 1.1052x over previous
#include <cuda_runtime.h>
#include <cuda_fp16.h>
#include <mma.h>
#include <cstdint>

using namespace nvcuda;

// Problem constants
#define MM     8192      // BATCH*SEQ
#define DMODEL 1024
#define DINNER 2048
#define DSTATE 16
#define NBATCH 4
#define SEQLEN 2048
#define NCHUNK 8
#define CLEN   256       // SEQLEN / NCHUNK

// ---------------- scratch (device globals: allocation-free) ----------------
__device__ float  g_u  [MM * DINNER];      // silu(x_proj) fp32 (scan/xproj)
__device__ __half g_uh [MM * DINNER];      // silu(x_proj) half (dt GEMM)
__device__ float  g_sz [MM * DINNER];      // silu(z)
__device__ float  g_dt [MM * DINNER];      // softplus(dt)
__device__ float  g_xd [MM * 32];          // [B|C] projection
__device__ __half g_ymh[MM * DINNER];      // y * silu(z) half (out GEMM)
__device__ __half g_xh [MM * DMODEL];      // half x
__device__ __half g_w1 [DMODEL * 4096];    // half W_in
__device__ __half g_w2 [DINNER * DINNER];  // half W_dt
__device__ __half g_w3 [DINNER * DMODEL];  // half W_out
__device__ float  g_hend  [NBATCH * NCHUNK * DINNER * DSTATE];  // local h_end
__device__ float  g_hstart[NBATCH * NCHUNK * DINNER * DSTATE];  // chunk h_start
__device__ float  g_sdt   [NBATCH * NCHUNK * DINNER];           // per-chunk sum dt

__device__ __forceinline__ float siluf(float v) { return v / (1.f + __expf(-v)); }
__device__ __forceinline__ float softplusf(float v) {
    return fmaxf(v, 0.f) + log1pf(__expf(-fabsf(v)));
}
__device__ __forceinline__ float ex2(float x) {
    float r; asm("ex2.approx.f32 %0, %1;" : "=f"(r) : "f"(x)); return r;
}

// ---------------- cp.async helpers ----------------------------------------
__device__ __forceinline__ void cp16(void* s, const void* g) {
    unsigned sa = (unsigned)__cvta_generic_to_shared(s);
    asm volatile("cp.async.cg.shared.global [%0], [%1], 16;\n" :: "r"(sa), "l"(g));
}
__device__ __forceinline__ void cp_commit() {
    asm volatile("cp.async.commit_group;\n" ::: "memory");
}
template<int N> __device__ __forceinline__ void cp_wait() {
    asm volatile("cp.async.wait_group %0;\n" :: "n"(N) : "memory");
}

// ---------------- fp16 WMMA GEMM (unchanged from R5) ------------------------
constexpr int AS_STRIDE = 40;
constexpr int BS_STRIDE = 136;
constexpr int AS_TILE   = 128 * AS_STRIDE;
constexpr int BS_TILE   = 32 * BS_STRIDE;
constexpr int EPI_BYTES = 8 * 256 * 4;
constexpr int GEMM_SMEM_BYTES =
    (2 * AS_TILE + 2 * BS_TILE) * 2 + EPI_BYTES;   // 46080 B -> 4 CTAs/SM

template<int EPI>
__global__ __launch_bounds__(256) void gemm_fp16(
    const __half* __restrict__ A, const __half* __restrict__ B,
    const float* __restrict__ bias,
    float* __restrict__ out0, float* __restrict__ out1,
    __half* __restrict__ out0h,
    int M, int N, int K)
{
    extern __shared__ char smem[];
    __half* As = (__half*)smem;
    __half* Bs = (__half*)smem + 2 * AS_TILE;
    float*  Epi = (float*)(smem + (2 * AS_TILE + 2 * BS_TILE) * 2);

    const int tid  = threadIdx.x;
    const int wid  = tid >> 5;
    const int lane = tid & 31;
    const int wm   = wid >> 2;
    const int wn   = wid & 3;
    const int m0   = blockIdx.y * 128;
    const int n0   = blockIdx.x * 128;

    const int arow = tid >> 2;
    const int ac16 = tid & 3;
    const int brow = tid >> 4;
    const int bc16 = tid & 15;

    wmma::fragment<wmma::accumulator, 16, 16, 16, float> acc[4][2];
    #pragma unroll
    for (int i = 0; i < 4; i++)
        #pragma unroll
        for (int j = 0; j < 2; j++)
            wmma::fill_fragment(acc[i][j], 0.f);

    const int NIT = K >> 5;

    auto load_ab = [&](int buf, int k0) {
        __half* da = As + buf * AS_TILE;
        __half* db = Bs + buf * BS_TILE;
        #pragma unroll
        for (int r = 0; r < 2; r++) {
            int row = arow + r * 64;
            cp16(&da[row * AS_STRIDE + ac16 * 8],
                 &A[(size_t)(m0 + row) * K + k0 + ac16 * 8]);
        }
        #pragma unroll
        for (int r = 0; r < 2; r++) {
            int row = brow + r * 16;
            cp16(&db[row * BS_STRIDE + bc16 * 8],
                 &B[(size_t)(k0 + row) * N + n0 + bc16 * 8]);
        }
        cp_commit();
    };

    load_ab(0, 0);

    for (int it = 0; it < NIT; it++) {
        const int buf = it & 1;
        if (it + 1 < NIT) {
            load_ab(buf ^ 1, (it + 1) << 5);
            cp_wait<1>();
        } else {
            cp_wait<0>();
        }
        __syncthreads();

        const __half* ca = As + buf * AS_TILE;
        const __half* cb = Bs + buf * BS_TILE;
        #pragma unroll
        for (int kk = 0; kk < 32; kk += 16) {
            wmma::fragment<wmma::matrix_a, 16, 16, 16, __half, wmma::row_major> af[4];
            wmma::fragment<wmma::matrix_b, 16, 16, 16, __half, wmma::row_major> bf[2];
            #pragma unroll
            for (int i = 0; i < 4; i++)
                wmma::load_matrix_sync(af[i],
                    &ca[(wm * 64 + i * 16) * AS_STRIDE + kk], AS_STRIDE);
            #pragma unroll
            for (int j = 0; j < 2; j++)
                wmma::load_matrix_sync(bf[j],
                    &cb[kk * BS_STRIDE + wn * 32 + j * 16], BS_STRIDE);
            #pragma unroll
            for (int i = 0; i < 4; i++)
                #pragma unroll
                for (int j = 0; j < 2; j++)
                    wmma::mma_sync(acc[i][j], af[i], bf[j], acc[i][j]);
        }
        __syncthreads();
    }

    float* EpiW = Epi + wid * 256;
    #pragma unroll
    for (int i = 0; i < 4; i++) {
        #pragma unroll
        for (int j = 0; j < 2; j++) {
            wmma::store_matrix_sync(EpiW, acc[i][j], 16, wmma::mem_row_major);
            __syncwarp();
            int gr0 = m0 + wm * 64 + i * 16;
            int gc0 = n0 + wn * 32 + j * 16;
            #pragma unroll
            for (int e = 0; e < 8; e++) {
                int idx = lane + e * 32;
                int r = idx >> 4, c = idx & 15;
                int gr = gr0 + r, gc = gc0 + c;
                float v = EpiW[r * 16 + c] + bias[gc];
                if (EPI == 0) {
                    float sv = siluf(v);
                    if (gc < DINNER) {
                        size_t o = (size_t)gr * DINNER + gc;
                        out0 [o] = sv;
                        out0h[o] = __float2half(sv);
                    } else {
                        out1[(size_t)gr * DINNER + gc - DINNER] = sv;
                    }
                } else if (EPI == 1) {
                    out0[(size_t)gr * DINNER + gc] = softplusf(v);
                } else {
                    out0[(size_t)gr * (size_t)N + gc] = v;
                }
            }
            __syncwarp();
        }
    }
}

// ---------------- prep: fp32 -> fp16 copies --------------------------------
__global__ __launch_bounds__(256) void half_copy(
    const float* __restrict__ src, __half* __restrict__ dst)
{
    int i = (blockIdx.x * 256 + threadIdx.x) * 8;
    float4 a = *(const float4*)&src[i];
    float4 b = *(const float4*)&src[i + 4];
    __half2 h[4];
    h[0] = __floats2half2_rn(a.x, a.y);
    h[1] = __floats2half2_rn(a.z, a.w);
    h[2] = __floats2half2_rn(b.x, b.y);
    h[3] = __floats2half2_rn(b.z, b.w);
    *(uint4*)&dst[i] = *(uint4*)h;
}

// ---------------- skinny projection: xdbl = u @ W_xproj + b ----------------
__global__ __launch_bounds__(256) void xproj_kernel(
    const float* __restrict__ u, const float* __restrict__ W,
    const float* __restrict__ bias, float* __restrict__ xdbl)
{
    __shared__ float Ws[32][33];
    const int wid  = threadIdx.x >> 5;
    const int lane = threadIdx.x & 31;
    const int row  = blockIdx.x * 8 + wid;

    float acc = 0.f;
    for (int k0 = 0; k0 < DINNER; k0 += 32) {
        #pragma unroll
        for (int r = 0; r < 4; r++) {
            int idx = threadIdx.x + r * 256;
            Ws[idx >> 5][idx & 31] = W[(size_t)(k0 + (idx >> 5)) * 32 + (idx & 31)];
        }
        __syncthreads();
        float a = u[(size_t)row * DINNER + k0 + lane];
        #pragma unroll
        for (int i = 0; i < 32; i++)
            acc = fmaf(__shfl_sync(0xffffffffu, a, i), Ws[i][lane], acc);
        __syncthreads();
    }
    xdbl[(size_t)row * 32 + lane] = acc + bias[lane];
}

// ---------------- chunked selective scan ------------------------------------
// Layout (both passes): CTA = (d-block of 64, chunk c, batch b), 256 threads,
// warp = 8 d x 4 lanes, lane owns 4 states.

// Pass 1: local recurrence with h0=0 over chunk -> h_end_local, sum(dt).
__global__ __launch_bounds__(256) void scan_pass1(
    const float* __restrict__ u, const float* __restrict__ dt,
    const float* __restrict__ xdbl, const float* __restrict__ A_log,
    float* __restrict__ hend, float* __restrict__ sdtg)
{
    __shared__ float XB[32][16];
    __shared__ float Us[32][64];
    __shared__ float Ts[32][64];

    const int b    = blockIdx.z;
    const int c    = blockIdx.y;
    const int d0   = blockIdx.x * 64;
    const int tid  = threadIdx.x;
    const int wid  = tid >> 5;
    const int lane = tid & 31;
    const int dq   = lane >> 2;
    const int sq   = lane & 3;
    const int dl   = wid * 8 + dq;
    const int d    = d0 + dl;

    float Ap[4], h[4] = {0.f, 0.f, 0.f, 0.f};
    #pragma unroll
    for (int i = 0; i < 4; i++)
        Ap[i] = -__expf(A_log[d * DSTATE + sq * 4 + i]) * 1.4426950408889634f;
    float sdt = 0.f;
    const size_t base = (size_t)b * SEQLEN * DINNER;
    const int tstart = c * CLEN;

    for (int t0 = tstart; t0 < tstart + CLEN; t0 += 32) {
        #pragma unroll
        for (int r = 0; r < 2; r++) {
            int idx = tid + r * 256;
            XB[idx >> 4][idx & 15] =
                xdbl[((size_t)b * SEQLEN + t0 + (idx >> 4)) * 32 + (idx & 15)];
        }
        #pragma unroll
        for (int r = 0; r < 8; r++) {
            int idx = tid + r * 256;
            int tt = idx >> 6, j = idx & 63;
            size_t g = base + (size_t)(t0 + tt) * DINNER + d0 + j;
            Us[tt][j] = u[g];
            Ts[tt][j] = dt[g];
        }
        __syncthreads();

        #pragma unroll 4
        for (int t = 0; t < 32; t++) {
            float dtv = Ts[t][dl];
            float du  = dtv * Us[t][dl];
            sdt += dtv;
            #pragma unroll
            for (int i = 0; i < 4; i++) {
                float e = ex2(dtv * Ap[i]);
                h[i] = fmaf(h[i], e, du * XB[t][sq * 4 + i]);
            }
        }
        __syncthreads();
    }

    size_t ho = ((size_t)(b * NCHUNK + c) * DINNER + d) * DSTATE + sq * 4;
    *(float4*)&hend[ho] = make_float4(h[0], h[1], h[2], h[3]);
    if (sq == 0) sdtg[(size_t)(b * NCHUNK + c) * DINNER + d] = sdt;
}

// Fix: sequential chain over chunks. thread = one (b,d,s).
__global__ __launch_bounds__(256) void scan_fix(
    const float* __restrict__ A_log, const float* __restrict__ hend,
    const float* __restrict__ sdtg, float* __restrict__ hstart)
{
    int idx = blockIdx.x * 256 + threadIdx.x;   // NBATCH*DINNER*DSTATE
    int s = idx & 15;
    int d = (idx >> 4) & (DINNER - 1);
    int b = idx >> 15;
    float Ap = -__expf(A_log[d * DSTATE + s]) * 1.4426950408889634f;
    float hs = 0.f;
    hstart[((size_t)(b * NCHUNK) * DINNER + d) * DSTATE + s] = 0.f;
    #pragma unroll
    for (int c = 1; c < NCHUNK; c++) {
        size_t pc = (size_t)(b * NCHUNK + c - 1) * DINNER + d;
        float P = ex2(Ap * sdtg[pc]);
        hs = fmaf(P, hs, hend[pc * DSTATE + s]);
        hstart[((size_t)(b * NCHUNK + c) * DINNER + d) * DSTATE + s] = hs;
    }
}

// Pass 2: full scan within chunk, seeded with h_start; fused * silu(z).
__global__ __launch_bounds__(256) void scan_pass2(
    const float* __restrict__ u, const float* __restrict__ dt,
    const float* __restrict__ xdbl, const float* __restrict__ sz,
    const float* __restrict__ A_log, const float* __restrict__ Dp,
    const float* __restrict__ hstart, __half* __restrict__ ymh)
{
    __shared__ float XD[32][32];
    __shared__ float Us[32][64];
    __shared__ float Ts[32][64];
    __shared__ float Zs[32][64];

    const int b    = blockIdx.z;
    const int c    = blockIdx.y;
    const int d0   = blockIdx.x * 64;
    const int tid  = threadIdx.x;
    const int wid  = tid >> 5;
    const int lane = tid & 31;
    const int dq   = lane >> 2;
    const int sq   = lane & 3;
    const int dl   = wid * 8 + dq;
    const int d    = d0 + dl;

    float Ap[4], h[4];
    #pragma unroll
    for (int i = 0; i < 4; i++)
        Ap[i] = -__expf(A_log[d * DSTATE + sq * 4 + i]) * 1.4426950408889634f;
    {
        float4 h0 = *(const float4*)
            &hstart[((size_t)(b * NCHUNK + c) * DINNER + d) * DSTATE + sq * 4];
        h[0] = h0.x; h[1] = h0.y; h[2] = h0.z; h[3] = h0.w;
    }
    const float Dv = Dp[d];
    const size_t base = (size_t)b * SEQLEN * DINNER;
    const int tstart = c * CLEN;

    for (int t0 = tstart; t0 < tstart + CLEN; t0 += 32) {
        #pragma unroll
        for (int r = 0; r < 4; r++) {
            int idx = tid + r * 256;
            XD[idx >> 5][idx & 31] =
                xdbl[((size_t)b * SEQLEN + t0 + (idx >> 5)) * 32 + (idx & 31)];
        }
        #pragma unroll
        for (int r = 0; r < 8; r++) {
            int idx = tid + r * 256;
            int tt = idx >> 6, j = idx & 63;
            size_t g = base + (size_t)(t0 + tt) * DINNER + d0 + j;
            Us[tt][j] = u[g];
            Ts[tt][j] = dt[g];
            Zs[tt][j] = sz[g];
        }
        __syncthreads();

        #pragma unroll 4
        for (int t = 0; t < 32; t++) {
            float dtv = Ts[t][dl];
            float uv  = Us[t][dl];
            float du  = dtv * uv;
            float p   = 0.f;
            #pragma unroll
            for (int i = 0; i < 4; i++) {
                float e = ex2(dtv * Ap[i]);
                h[i] = fmaf(h[i], e, du * XD[t][sq * 4 + i]);
                p    = fmaf(h[i], XD[t][16 + sq * 4 + i], p);
            }
            p += __shfl_xor_sync(0xffffffffu, p, 1);
            p += __shfl_xor_sync(0xffffffffu, p, 2);
            if (sq == 0) {
                float y = p + Dv * uv;
                ymh[base + (size_t)(t0 + t) * DINNER + d] = __float2half(y * Zs[t][dl]);
            }
        }
        __syncthreads();
    }
}

// ---------------- launch ---------------------------------------------------
extern "C" void kernel_launch(void* const* d_in, const int* in_sizes, int n_in,
                              void* d_out, int out_size)
{
    const float* x     = (const float*)d_in[0];
    const float* W_in  = (const float*)d_in[1];
    const float* b_in  = (const float*)d_in[2];
    const float* W_xp  = (const float*)d_in[3];
    const float* b_xp  = (const float*)d_in[4];
    const float* W_dt  = (const float*)d_in[5];
    const float* b_dt  = (const float*)d_in[6];
    const float* W_out = (const float*)d_in[7];
    const float* b_out = (const float*)d_in[8];
    const float* A_log = (const float*)d_in[9];
    const float* D_par = (const float*)d_in[10];
    float* out = (float*)d_out;

    float *u, *sz, *dtb, *xd, *hend, *hstart, *sdt;
    __half *uh, *ymh, *xh, *w1, *w2, *w3;
    cudaGetSymbolAddress((void**)&u,   g_u);
    cudaGetSymbolAddress((void**)&uh,  g_uh);
    cudaGetSymbolAddress((void**)&sz,  g_sz);
    cudaGetSymbolAddress((void**)&dtb, g_dt);
    cudaGetSymbolAddress((void**)&xd,  g_xd);
    cudaGetSymbolAddress((void**)&ymh, g_ymh);
    cudaGetSymbolAddress((void**)&xh,  g_xh);
    cudaGetSymbolAddress((void**)&w1,  g_w1);
    cudaGetSymbolAddress((void**)&w2,  g_w2);
    cudaGetSymbolAddress((void**)&w3,  g_w3);
    cudaGetSymbolAddress((void**)&hend,   g_hend);
    cudaGetSymbolAddress((void**)&hstart, g_hstart);
    cudaGetSymbolAddress((void**)&sdt,    g_sdt);

    cudaFuncSetAttribute(gemm_fp16<0>, cudaFuncAttributeMaxDynamicSharedMemorySize, GEMM_SMEM_BYTES);
    cudaFuncSetAttribute(gemm_fp16<1>, cudaFuncAttributeMaxDynamicSharedMemorySize, GEMM_SMEM_BYTES);
    cudaFuncSetAttribute(gemm_fp16<2>, cudaFuncAttributeMaxDynamicSharedMemorySize, GEMM_SMEM_BYTES);

    // prep: half copies of x and weights
    half_copy<<<MM * DMODEL / 2048, 256>>>(x, xh);
    half_copy<<<DMODEL * 4096 / 2048, 256>>>(W_in, w1);
    half_copy<<<DINNER * DINNER / 2048, 256>>>(W_dt, w2);
    half_copy<<<DINNER * DMODEL / 2048, 256>>>(W_out, w3);

    dim3 blk(256);

    // 1) xz = x @ W_in + b_in; split+silu -> u (f32 + half), sz (f32)
    gemm_fp16<0><<<dim3(4096 / 128, MM / 128), blk, GEMM_SMEM_BYTES>>>(
        xh, w1, b_in, u, sz, uh, MM, 4096, DMODEL);

    // 2) xdbl = u @ W_xproj + b_xproj  (fp32 path)
    xproj_kernel<<<MM / 8, 256>>>(u, W_xp, b_xp, xd);

    // 3) dt = softplus(u @ W_dt + b_dt)
    gemm_fp16<1><<<dim3(DINNER / 128, MM / 128), blk, GEMM_SMEM_BYTES>>>(
        uh, w2, b_dt, dtb, nullptr, nullptr, MM, DINNER, DINNER);

    // 4) chunked selective scan + fuse * silu(z) -> ym half
    scan_pass1<<<dim3(DINNER / 64, NCHUNK - 1, NBATCH), 256>>>(
        u, dtb, xd, A_log, hend, sdt);
    scan_fix<<<NBATCH * DINNER * DSTATE / 256, 256>>>(A_log, hend, sdt, hstart);
    scan_pass2<<<dim3(DINNER / 64, NCHUNK, NBATCH), 256>>>(
        u, dtb, xd, sz, A_log, D_par, hstart, ymh);

    // 5) out = ym @ W_out + b_out
    gemm_fp16<2><<<dim3(DMODEL / 128, MM / 128), blk, GEMM_SMEM_BYTES>>>(
        ymh, w3, b_out, out, nullptr, nullptr, MM, DMODEL, DINNER);
}